// round 2
// baseline (speedup 1.0000x reference)
#include <cuda_runtime.h>

// ---------------------------------------------------------------------------
// 3-layer GCN:  relu(gcn(x,Wr)) -> relu(gcn(.,W2)) -> gcn(.,W1)
// gcn(x,W): out[v] = dis[v]*( sum_{s->v} h_s[s] + h_s[v] ) + b
//           where h_s = (x@W) * dis[row],  dis = rsqrt(indeg+1)
// ---------------------------------------------------------------------------

#define N_MAX 50000
#define E_MAX 640000
#define D     128

// scratch (static device memory: allocation-free rule)
__device__ float g_h[N_MAX * D];        // h_scaled
__device__ float g_a[N_MAX * D];        // layer activation
__device__ float g_dis_role[N_MAX];
__device__ float g_dis_norm[N_MAX];
__device__ int   g_cnt_role[N_MAX];
__device__ int   g_cnt_norm[N_MAX];
__device__ int   g_fill_role[N_MAX];
__device__ int   g_fill_norm[N_MAX];
__device__ int   g_rowptr_role[N_MAX + 1];
__device__ int   g_rowptr_norm[N_MAX + 1];
__device__ int   g_col_role[E_MAX];
__device__ int   g_col_norm[E_MAX];

// ---------------------------------------------------------------------------
__global__ void zero_kernel(int n) {
    int i = blockIdx.x * blockDim.x + threadIdx.x;
    if (i < n) {
        g_cnt_role[i]  = 0;
        g_cnt_norm[i]  = 0;
        g_fill_role[i] = 0;
        g_fill_norm[i] = 0;
    }
}

__global__ void count_kernel(const int* __restrict__ dst, int E, int* __restrict__ cnt) {
    int e = blockIdx.x * blockDim.x + threadIdx.x;
    if (e < E) atomicAdd(&cnt[dst[e]], 1);
}

__global__ void dis_kernel(int n) {
    int i = blockIdx.x * blockDim.x + threadIdx.x;
    if (i < n) {
        g_dis_role[i] = rsqrtf((float)(g_cnt_role[i] + 1));
        g_dis_norm[i] = rsqrtf((float)(g_cnt_norm[i] + 1));
    }
}

// single-block chunked exclusive scan (n = 50000, 49 chunks of 1024)
__global__ void scan_kernel(const int* __restrict__ cnt, int* __restrict__ rowptr, int n) {
    __shared__ int sh[1024];
    int tid = threadIdx.x;
    int carry = 0;
    for (int base = 0; base < n; base += 1024) {
        int i = base + tid;
        int v = (i < n) ? cnt[i] : 0;
        sh[tid] = v;
        __syncthreads();
        // Hillis-Steele inclusive scan
        for (int off = 1; off < 1024; off <<= 1) {
            int t = (tid >= off) ? sh[tid - off] : 0;
            __syncthreads();
            sh[tid] += t;
            __syncthreads();
        }
        if (i < n) rowptr[i] = carry + sh[tid] - v;   // exclusive
        int total = sh[1023];
        __syncthreads();
        carry += total;
    }
    if (tid == 0) rowptr[n] = carry;
}

__global__ void scatter_kernel(const int* __restrict__ src, const int* __restrict__ dst,
                               int E, const int* __restrict__ rowptr,
                               int* __restrict__ fill, int* __restrict__ col) {
    int e = blockIdx.x * blockDim.x + threadIdx.x;
    if (e < E) {
        int d = dst[e];
        int pos = rowptr[d] + atomicAdd(&fill[d], 1);
        col[pos] = src[e];
    }
}

// ---------------------------------------------------------------------------
// GEMM (M x 128) @ (128 x 128), epilogue scales each row by dis[row].
// BM=64, BK=32, 256 threads, 8x4 microtile per thread.
// ---------------------------------------------------------------------------
__global__ __launch_bounds__(256) void gemm_scale_kernel(
    const float* __restrict__ X, const float* __restrict__ W,
    const float* __restrict__ dis, float* __restrict__ H, int M)
{
    __shared__ float As[64 * 32];     // [row][k] 8 KB
    __shared__ float Ws[32 * 128];    // [k][col] 16 KB

    const int t  = threadIdx.x;
    const int tx = t & 31;            // col group: cols tx*4 .. tx*4+3
    const int ty = t >> 5;            // row group: rows ty*8 .. ty*8+7
    const int row0 = blockIdx.x * 64;

    float4 acc[8];
    #pragma unroll
    for (int i = 0; i < 8; i++) acc[i] = make_float4(0.f, 0.f, 0.f, 0.f);

    const float4* W4 = (const float4*)W;
    float4* Ws4 = (float4*)Ws;
    float4* As4 = (float4*)As;

    for (int k0 = 0; k0 < 128; k0 += 32) {
        // load W tile: 32x128 floats = 1024 float4, 4 per thread
        #pragma unroll
        for (int i = 0; i < 4; i++) {
            int f4 = i * 256 + t;                       // kk*32 + c4
            Ws4[f4] = W4[k0 * 32 + f4];
        }
        // load A tile: 64x32 floats = 512 float4, 2 per thread
        #pragma unroll
        for (int it = 0; it < 2; it++) {
            int r = (t >> 3) + it * 32;                 // 0..63
            int c = t & 7;                              // float4 within row
            int row = row0 + r;
            float4 v = make_float4(0.f, 0.f, 0.f, 0.f);
            if (row < M) v = ((const float4*)X)[row * 32 + (k0 >> 2) + c];
            As4[r * 8 + c] = v;
        }
        __syncthreads();

        #pragma unroll 8
        for (int kk = 0; kk < 32; kk++) {
            float4 wv = Ws4[kk * 32 + tx];
            #pragma unroll
            for (int i = 0; i < 8; i++) {
                float av = As[(ty * 8 + i) * 32 + kk];  // warp-broadcast
                acc[i].x += av * wv.x;
                acc[i].y += av * wv.y;
                acc[i].z += av * wv.z;
                acc[i].w += av * wv.w;
            }
        }
        __syncthreads();
    }

    #pragma unroll
    for (int i = 0; i < 8; i++) {
        int row = row0 + ty * 8 + i;
        if (row < M) {
            float s = dis[row];
            float4 o = acc[i];
            o.x *= s; o.y *= s; o.z *= s; o.w *= s;
            ((float4*)H)[row * 32 + tx] = o;
        }
    }
}

// ---------------------------------------------------------------------------
// Aggregation: warp per node, lane holds channels [lane*4, lane*4+4)
// out[v] = dis[v]*( h_s[v] + sum_j h_s[col[j]] ) + b ; optional relu
// ---------------------------------------------------------------------------
template <bool RELU>
__global__ __launch_bounds__(256) void aggregate_kernel(
    const float* __restrict__ h, const int* __restrict__ rowptr,
    const int* __restrict__ col, const float* __restrict__ dis,
    const float* __restrict__ bias, float* __restrict__ out, int n)
{
    int w    = (blockIdx.x * blockDim.x + threadIdx.x) >> 5;
    int lane = threadIdx.x & 31;
    if (w >= n) return;

    const float4* h4 = (const float4*)h;
    float4 acc = __ldg(&h4[w * 32 + lane]);   // self loop

    int beg = rowptr[w], end = rowptr[w + 1];
    for (int j = beg; j < end; j++) {
        int s = __ldg(&col[j]);
        float4 t = __ldg(&h4[s * 32 + lane]);
        acc.x += t.x; acc.y += t.y; acc.z += t.z; acc.w += t.w;
    }

    float dv = dis[w];
    float4 bv = ((const float4*)bias)[lane];
    acc.x = acc.x * dv + bv.x;
    acc.y = acc.y * dv + bv.y;
    acc.z = acc.z * dv + bv.z;
    acc.w = acc.w * dv + bv.w;
    if (RELU) {
        acc.x = fmaxf(acc.x, 0.f); acc.y = fmaxf(acc.y, 0.f);
        acc.z = fmaxf(acc.z, 0.f); acc.w = fmaxf(acc.w, 0.f);
    }
    ((float4*)out)[w * 32 + lane] = acc;
}

// ---------------------------------------------------------------------------
extern "C" void kernel_launch(void* const* d_in, const int* in_sizes, int n_in,
                              void* d_out, int out_size)
{
    const float* x      = (const float*)d_in[0];
    const float* W_role = (const float*)d_in[1];
    const float* b_role = (const float*)d_in[2];
    const float* W2     = (const float*)d_in[3];
    const float* b2     = (const float*)d_in[4];
    const float* W1     = (const float*)d_in[5];
    const float* b1     = (const float*)d_in[6];
    const int*   ei_nrm = (const int*)d_in[7];
    const int*   ei_rol = (const int*)d_in[8];

    const int n = in_sizes[0] / D;       // 50000
    const int E = in_sizes[7] / 2;       // 640000

    const int* src_n = ei_nrm;
    const int* dst_n = ei_nrm + E;
    const int* src_r = ei_rol;
    const int* dst_r = ei_rol + E;

    // device symbol addresses (resolved at module load; no runtime query needed)
    float *h_s, *act, *dis_r, *dis_n, *dum;
    int *cnt_r, *cnt_n, *fill_r, *fill_n, *rp_r, *rp_n, *col_r, *col_n;
    cudaGetSymbolAddress((void**)&h_s,    g_h);
    cudaGetSymbolAddress((void**)&act,    g_a);
    cudaGetSymbolAddress((void**)&dis_r,  g_dis_role);
    cudaGetSymbolAddress((void**)&dis_n,  g_dis_norm);
    cudaGetSymbolAddress((void**)&cnt_r,  g_cnt_role);
    cudaGetSymbolAddress((void**)&cnt_n,  g_cnt_norm);
    cudaGetSymbolAddress((void**)&fill_r, g_fill_role);
    cudaGetSymbolAddress((void**)&fill_n, g_fill_norm);
    cudaGetSymbolAddress((void**)&rp_r,   g_rowptr_role);
    cudaGetSymbolAddress((void**)&rp_n,   g_rowptr_norm);
    cudaGetSymbolAddress((void**)&col_r,  g_col_role);
    cudaGetSymbolAddress((void**)&col_n,  g_col_norm);
    (void)dum;

    const int TB = 256;
    const int nbN = (n + TB - 1) / TB;
    const int nbE = (E + TB - 1) / TB;

    // ---- graph preprocessing (both graphs) ----
    zero_kernel<<<nbN, TB>>>(n);
    count_kernel<<<nbE, TB>>>(dst_r, E, cnt_r);
    count_kernel<<<nbE, TB>>>(dst_n, E, cnt_n);
    dis_kernel<<<nbN, TB>>>(n);
    scan_kernel<<<1, 1024>>>(cnt_r, rp_r, n);
    scan_kernel<<<1, 1024>>>(cnt_n, rp_n, n);
    scatter_kernel<<<nbE, TB>>>(src_r, dst_r, E, rp_r, fill_r, col_r);
    scatter_kernel<<<nbE, TB>>>(src_n, dst_n, E, rp_n, fill_n, col_n);

    const int gemmBlocks = (n + 63) / 64;
    const int aggBlocks  = (n + 7) / 8;     // 8 warps/block, warp per node

    // ---- layer 1: role graph, relu ----
    gemm_scale_kernel<<<gemmBlocks, 256>>>(x, W_role, dis_r, h_s, n);
    aggregate_kernel<true><<<aggBlocks, 256>>>(h_s, rp_r, col_r, dis_r, b_role, act, n);

    // ---- layer 2: normal graph, relu ----
    gemm_scale_kernel<<<gemmBlocks, 256>>>(act, W2, dis_n, h_s, n);
    aggregate_kernel<true><<<aggBlocks, 256>>>(h_s, rp_n, col_n, dis_n, b2, act, n);

    // ---- layer 3: normal graph, no relu, write d_out ----
    gemm_scale_kernel<<<gemmBlocks, 256>>>(act, W1, dis_n, h_s, n);
    aggregate_kernel<false><<<aggBlocks, 256>>>(h_s, rp_n, col_n, dis_n, b1,
                                                (float*)d_out, n);
}

// round 3
// speedup vs baseline: 1.3995x; 1.3995x over previous
#include <cuda_runtime.h>

// ---------------------------------------------------------------------------
// 3-layer GCN:  relu(gcn(x,Wr)) -> relu(gcn(.,W2)) -> gcn(.,W1)
// gcn(x,W): out[v] = dis[v]*( sum_{s->v} h_s[s] + h_s[v] ) + b
//           where h_s = (x@W) * dis[row],  dis = rsqrt(indeg+1)
// ---------------------------------------------------------------------------

#define N_MAX 50000
#define E_MAX 640000
#define D     128
#define NCH_MAX 64          // chunks of 1024 nodes (50000 -> 49)

// scratch (static device memory: allocation-free rule)
__device__ float g_h[N_MAX * D];        // h_scaled
__device__ float g_a[N_MAX * D];        // layer activation
__device__ float g_dis_role[N_MAX];
__device__ float g_dis_norm[N_MAX];
__device__ int   g_cnt_role[N_MAX];
__device__ int   g_cnt_norm[N_MAX];
__device__ int   g_fill_role[N_MAX];
__device__ int   g_fill_norm[N_MAX];
__device__ int   g_loc_role[N_MAX];     // exclusive prefix within 1024-chunk
__device__ int   g_loc_norm[N_MAX];
__device__ int   g_tot[2 * NCH_MAX];    // per-chunk totals   [graph][chunk]
__device__ int   g_off[2 * NCH_MAX];    // exclusive chunk offsets
__device__ int   g_col_role[E_MAX];
__device__ int   g_col_norm[E_MAX];

// ---------------------------------------------------------------------------
__global__ void zero_kernel(int n) {
    int i = blockIdx.x * blockDim.x + threadIdx.x;
    if (i < n) {
        g_cnt_role[i]  = 0;
        g_cnt_norm[i]  = 0;
        g_fill_role[i] = 0;
        g_fill_norm[i] = 0;
    }
}

// one launch counts both graphs
__global__ void count_kernel(const int* __restrict__ dst_n,
                             const int* __restrict__ dst_r, int E) {
    int e = blockIdx.x * blockDim.x + threadIdx.x;
    if (e < E) {
        atomicAdd(&g_cnt_norm[dst_n[e]], 1);
        atomicAdd(&g_cnt_role[dst_r[e]], 1);
    }
}

// grid (nch, 2): per-chunk warp-shuffle scan; also computes dis = rsqrt(cnt+1)
__global__ __launch_bounds__(1024) void scan_local_kernel(int n) {
    const int g = blockIdx.y;
    const int* __restrict__ cnt = g ? g_cnt_role : g_cnt_norm;
    int* __restrict__ loc       = g ? g_loc_role : g_loc_norm;
    float* __restrict__ dis     = g ? g_dis_role : g_dis_norm;

    __shared__ int wsum[32];
    int tid  = threadIdx.x;
    int lane = tid & 31, wid = tid >> 5;
    int i = (blockIdx.x << 10) + tid;
    int v = (i < n) ? cnt[i] : 0;

    // warp inclusive scan
    int s = v;
    #pragma unroll
    for (int o = 1; o < 32; o <<= 1) {
        int t = __shfl_up_sync(0xffffffffu, s, o);
        if (lane >= o) s += t;
    }
    if (lane == 31) wsum[wid] = s;
    __syncthreads();
    if (wid == 0) {
        int w = wsum[lane];
        #pragma unroll
        for (int o = 1; o < 32; o <<= 1) {
            int t = __shfl_up_sync(0xffffffffu, w, o);
            if (lane >= o) w += t;
        }
        wsum[lane] = w;   // inclusive over warps
    }
    __syncthreads();
    int woff = (wid == 0) ? 0 : wsum[wid - 1];
    int ex = s - v + woff;                 // block-local exclusive
    if (i < n) {
        loc[i] = ex;
        dis[i] = rsqrtf((float)(v + 1));
    }
    if (tid == 0) g_tot[g * NCH_MAX + blockIdx.x] = wsum[31];
}

// 1 block, 64 threads: warp g scans its graph's chunk totals
__global__ void scan_mid_kernel(int nch) {
    int g = threadIdx.x >> 5, lane = threadIdx.x & 31;
    int carry = 0;
    for (int c0 = 0; c0 < nch; c0 += 32) {
        int idx = c0 + lane;
        int v = (idx < nch) ? g_tot[g * NCH_MAX + idx] : 0;
        int s = v;
        #pragma unroll
        for (int o = 1; o < 32; o <<= 1) {
            int t = __shfl_up_sync(0xffffffffu, s, o);
            if (lane >= o) s += t;
        }
        if (idx < nch) g_off[g * NCH_MAX + idx] = carry + s - v;
        carry += __shfl_sync(0xffffffffu, s, 31);
    }
}

// grid (nbE, 2): scatter both graphs, computing final rowptr on the fly
__global__ void scatter_kernel(const int* __restrict__ src_n,
                               const int* __restrict__ dst_n,
                               const int* __restrict__ src_r,
                               const int* __restrict__ dst_r, int E) {
    const int g = blockIdx.y;
    const int* __restrict__ src = g ? src_r : src_n;
    const int* __restrict__ dst = g ? dst_r : dst_n;
    const int* __restrict__ loc = g ? g_loc_role : g_loc_norm;
    int* __restrict__ fill      = g ? g_fill_role : g_fill_norm;
    int* __restrict__ col       = g ? g_col_role : g_col_norm;
    const int* off = &g_off[g * NCH_MAX];

    int e = blockIdx.x * blockDim.x + threadIdx.x;
    if (e < E) {
        int d = dst[e];
        int pos = loc[d] + off[d >> 10] + atomicAdd(&fill[d], 1);
        col[pos] = src[e];
    }
}

// ---------------------------------------------------------------------------
// GEMM (M x 128) @ (128 x 128), epilogue scales each row by dis[row].
// BM=128, BN=128, BK=32, 256 threads, 8x8 microtile per thread.
// ---------------------------------------------------------------------------
__global__ __launch_bounds__(256, 2) void gemm_scale_kernel(
    const float* __restrict__ X, const float* __restrict__ W,
    const float* __restrict__ dis, float* __restrict__ H, int M)
{
    __shared__ float As[128 * 32];    // [row][k] 16 KB
    __shared__ float Ws[32 * 128];    // [k][col] 16 KB

    const int t  = threadIdx.x;
    const int tx = t & 15;            // cols tx*8 .. tx*8+7
    const int ty = t >> 4;            // rows ty*8 .. ty*8+7
    const int row0 = blockIdx.x * 128;

    float4 acc0[8], acc1[8];
    #pragma unroll
    for (int i = 0; i < 8; i++) {
        acc0[i] = make_float4(0.f, 0.f, 0.f, 0.f);
        acc1[i] = make_float4(0.f, 0.f, 0.f, 0.f);
    }

    const float4* X4 = (const float4*)X;
    const float4* W4 = (const float4*)W;
    float4* As4 = (float4*)As;
    float4* Ws4 = (float4*)Ws;

    for (int k0 = 0; k0 < 128; k0 += 32) {
        // W tile: 32x128 = 1024 float4, 4 per thread
        #pragma unroll
        for (int i = 0; i < 4; i++) {
            int f = i * 256 + t;
            Ws4[f] = W4[k0 * 32 + f];
        }
        // A tile: 128x32 = 1024 float4, 4 per thread
        #pragma unroll
        for (int i = 0; i < 4; i++) {
            int f = i * 256 + t;
            int r = f >> 3, c = f & 7;
            int row = row0 + r;
            float4 v = make_float4(0.f, 0.f, 0.f, 0.f);
            if (row < M) v = X4[row * 32 + (k0 >> 2) + c];
            As4[r * 8 + c] = v;
        }
        __syncthreads();

        #pragma unroll 8
        for (int kk = 0; kk < 32; kk++) {
            float4 w0 = Ws4[kk * 32 + tx * 2];
            float4 w1 = Ws4[kk * 32 + tx * 2 + 1];
            #pragma unroll
            for (int i = 0; i < 8; i++) {
                float a = As[(ty * 8 + i) * 32 + kk];   // 2-addr broadcast
                acc0[i].x += a * w0.x;  acc0[i].y += a * w0.y;
                acc0[i].z += a * w0.z;  acc0[i].w += a * w0.w;
                acc1[i].x += a * w1.x;  acc1[i].y += a * w1.y;
                acc1[i].z += a * w1.z;  acc1[i].w += a * w1.w;
            }
        }
        __syncthreads();
    }

    float4* H4 = (float4*)H;
    #pragma unroll
    for (int i = 0; i < 8; i++) {
        int row = row0 + ty * 8 + i;
        if (row < M) {
            float s = dis[row];
            float4 o0 = acc0[i], o1 = acc1[i];
            o0.x *= s; o0.y *= s; o0.z *= s; o0.w *= s;
            o1.x *= s; o1.y *= s; o1.z *= s; o1.w *= s;
            H4[row * 32 + tx * 2]     = o0;
            H4[row * 32 + tx * 2 + 1] = o1;
        }
    }
}

// ---------------------------------------------------------------------------
// Aggregation: warp per node, lane holds channels [lane*4, lane*4+4)
// rowptr computed on the fly from (loc, off). 4x edge unroll for MLP.
// ---------------------------------------------------------------------------
template <bool RELU>
__global__ __launch_bounds__(256) void aggregate_kernel(
    const float* __restrict__ h, const int* __restrict__ loc,
    const int* __restrict__ off, const int* __restrict__ col,
    const float* __restrict__ dis, const float* __restrict__ bias,
    float* __restrict__ out, int n, int E)
{
    int w    = (blockIdx.x * blockDim.x + threadIdx.x) >> 5;
    int lane = threadIdx.x & 31;
    if (w >= n) return;

    int beg = loc[w] + off[w >> 10];
    int end = (w + 1 < n) ? (loc[w + 1] + off[(w + 1) >> 10]) : E;

    const float4* h4 = (const float4*)h;
    float4 acc = __ldg(&h4[w * 32 + lane]);   // self loop

    int j = beg;
    for (; j + 4 <= end; j += 4) {
        int s0 = __ldg(&col[j]);
        int s1 = __ldg(&col[j + 1]);
        int s2 = __ldg(&col[j + 2]);
        int s3 = __ldg(&col[j + 3]);
        float4 a0 = __ldg(&h4[s0 * 32 + lane]);
        float4 a1 = __ldg(&h4[s1 * 32 + lane]);
        float4 a2 = __ldg(&h4[s2 * 32 + lane]);
        float4 a3 = __ldg(&h4[s3 * 32 + lane]);
        acc.x += (a0.x + a1.x) + (a2.x + a3.x);
        acc.y += (a0.y + a1.y) + (a2.y + a3.y);
        acc.z += (a0.z + a1.z) + (a2.z + a3.z);
        acc.w += (a0.w + a1.w) + (a2.w + a3.w);
    }
    for (; j < end; j++) {
        int s = __ldg(&col[j]);
        float4 a = __ldg(&h4[s * 32 + lane]);
        acc.x += a.x; acc.y += a.y; acc.z += a.z; acc.w += a.w;
    }

    float dv = dis[w];
    float4 bv = ((const float4*)bias)[lane];
    acc.x = acc.x * dv + bv.x;
    acc.y = acc.y * dv + bv.y;
    acc.z = acc.z * dv + bv.z;
    acc.w = acc.w * dv + bv.w;
    if (RELU) {
        acc.x = fmaxf(acc.x, 0.f); acc.y = fmaxf(acc.y, 0.f);
        acc.z = fmaxf(acc.z, 0.f); acc.w = fmaxf(acc.w, 0.f);
    }
    ((float4*)out)[w * 32 + lane] = acc;
}

// ---------------------------------------------------------------------------
extern "C" void kernel_launch(void* const* d_in, const int* in_sizes, int n_in,
                              void* d_out, int out_size)
{
    const float* x      = (const float*)d_in[0];
    const float* W_role = (const float*)d_in[1];
    const float* b_role = (const float*)d_in[2];
    const float* W2     = (const float*)d_in[3];
    const float* b2     = (const float*)d_in[4];
    const float* W1     = (const float*)d_in[5];
    const float* b1     = (const float*)d_in[6];
    const int*   ei_nrm = (const int*)d_in[7];
    const int*   ei_rol = (const int*)d_in[8];

    const int n = in_sizes[0] / D;       // 50000
    const int E = in_sizes[7] / 2;       // 640000

    const int* src_n = ei_nrm;
    const int* dst_n = ei_nrm + E;
    const int* src_r = ei_rol;
    const int* dst_r = ei_rol + E;

    float *h_s, *act, *dis_r, *dis_n;
    int *loc_r, *loc_n, *col_r, *col_n, *off_d;
    cudaGetSymbolAddress((void**)&h_s,   g_h);
    cudaGetSymbolAddress((void**)&act,   g_a);
    cudaGetSymbolAddress((void**)&dis_r, g_dis_role);
    cudaGetSymbolAddress((void**)&dis_n, g_dis_norm);
    cudaGetSymbolAddress((void**)&loc_r, g_loc_role);
    cudaGetSymbolAddress((void**)&loc_n, g_loc_norm);
    cudaGetSymbolAddress((void**)&col_r, g_col_role);
    cudaGetSymbolAddress((void**)&col_n, g_col_norm);
    cudaGetSymbolAddress((void**)&off_d, g_off);

    const int TB  = 256;
    const int nbN = (n + TB - 1) / TB;
    const int nbE = (E + TB - 1) / TB;
    const int nch = (n + 1023) >> 10;

    // ---- preprocessing: exactly 5 launches, so launch #5 (0-based) = gemm ----
    zero_kernel<<<nbN, TB>>>(n);
    count_kernel<<<nbE, TB>>>(dst_n, dst_r, E);
    scan_local_kernel<<<dim3(nch, 2), 1024>>>(n);
    scan_mid_kernel<<<1, 64>>>(nch);
    scatter_kernel<<<dim3(nbE, 2), TB>>>(src_n, dst_n, src_r, dst_r, E);

    const int gemmBlocks = (n + 127) / 128;
    const int aggBlocks  = (n + 7) / 8;   // 8 warps/block, warp per node

    // ---- layer 1: role graph, relu ----
    gemm_scale_kernel<<<gemmBlocks, 256>>>(x, W_role, dis_r, h_s, n);
    aggregate_kernel<true><<<aggBlocks, 256>>>(h_s, loc_r, off_d + NCH_MAX,
                                               col_r, dis_r, b_role, act, n, E);

    // ---- layer 2: normal graph, relu ----
    gemm_scale_kernel<<<gemmBlocks, 256>>>(act, W2, dis_n, h_s, n);
    aggregate_kernel<true><<<aggBlocks, 256>>>(h_s, loc_n, off_d,
                                               col_n, dis_n, b2, act, n, E);

    // ---- layer 3: normal graph, no relu, write d_out ----
    gemm_scale_kernel<<<gemmBlocks, 256>>>(act, W1, dis_n, h_s, n);
    aggregate_kernel<false><<<aggBlocks, 256>>>(h_s, loc_n, off_d,
                                                col_n, dis_n, b1,
                                                (float*)d_out, n, E);
}

// round 7
// speedup vs baseline: 1.8429x; 1.3168x over previous
#include <cuda_runtime.h>
#include <cuda_bf16.h>
#include <cstdint>
#include <stdint.h>

// ---------------------------------------------------------------------------
// 3-layer GCN:  relu(gcn(x,Wr)) -> relu(gcn(.,W2)) -> gcn(.,W1)
// gcn(x,W): out[v] = dis[v]*( sum_{s->v} h_s[s] + h_s[v] ) + b
//           where h_s = (x@W) * dis[row],  dis = rsqrt(indeg+1)
// GEMM runs on tensor cores via bf16 hi/lo split (3x mma, ~fp32 accuracy).
// ---------------------------------------------------------------------------

#define N_MAX 50000
#define E_MAX 640000
#define D     128
#define NCH_MAX 64

// scratch (static device memory: allocation-free rule)
__device__ float g_h[N_MAX * D];        // h_scaled
__device__ float g_a[N_MAX * D];        // layer activation
__device__ float g_dis_role[N_MAX];
__device__ float g_dis_norm[N_MAX];
__device__ int   g_cnt_role[N_MAX];
__device__ int   g_cnt_norm[N_MAX];
__device__ int   g_fill_role[N_MAX];
__device__ int   g_fill_norm[N_MAX];
__device__ int   g_loc_role[N_MAX];
__device__ int   g_loc_norm[N_MAX];
__device__ int   g_tot[2 * NCH_MAX];
__device__ int   g_off[2 * NCH_MAX];
__device__ int   g_col_role[E_MAX];
__device__ int   g_col_norm[E_MAX];
// split+transposed weights: [w][n][k] bf16 hi / lo
__device__ __align__(16) __nv_bfloat16 g_WTh[3 * D * D];
__device__ __align__(16) __nv_bfloat16 g_WTl[3 * D * D];

// ---------------------------------------------------------------------------
// prep: zero counters AND split/transpose the 3 weight matrices
__global__ void prep_kernel(const float* __restrict__ Wr,
                            const float* __restrict__ W2,
                            const float* __restrict__ W1, int n) {
    int i = blockIdx.x * blockDim.x + threadIdx.x;
    if (i < n) {
        g_cnt_role[i]  = 0;
        g_cnt_norm[i]  = 0;
        g_fill_role[i] = 0;
        g_fill_norm[i] = 0;
    }
    if (i < 3 * D * D) {
        int w = i >> 14, rem = i & 16383;
        int k = rem >> 7, nn = rem & 127;
        const float* W = (w == 0) ? Wr : (w == 1) ? W2 : W1;
        float v = W[k * D + nn];
        __nv_bfloat16 h = __float2bfloat16(v);
        __nv_bfloat16 l = __float2bfloat16(v - __bfloat162float(h));
        g_WTh[w * D * D + nn * D + k] = h;   // [n][k] layout (col-major B)
        g_WTl[w * D * D + nn * D + k] = l;
    }
}

__global__ void count_kernel(const int* __restrict__ dst_n,
                             const int* __restrict__ dst_r, int E) {
    int e = blockIdx.x * blockDim.x + threadIdx.x;
    if (e < E) {
        atomicAdd(&g_cnt_norm[dst_n[e]], 1);
        atomicAdd(&g_cnt_role[dst_r[e]], 1);
    }
}

// grid (nch, 2): per-chunk warp-shuffle scan; also computes dis = rsqrt(cnt+1)
__global__ __launch_bounds__(1024) void scan_local_kernel(int n) {
    const int g = blockIdx.y;
    const int* __restrict__ cnt = g ? g_cnt_role : g_cnt_norm;
    int* __restrict__ loc       = g ? g_loc_role : g_loc_norm;
    float* __restrict__ dis     = g ? g_dis_role : g_dis_norm;

    __shared__ int wsum[32];
    int tid  = threadIdx.x;
    int lane = tid & 31, wid = tid >> 5;
    int i = (blockIdx.x << 10) + tid;
    int v = (i < n) ? cnt[i] : 0;

    int s = v;
    #pragma unroll
    for (int o = 1; o < 32; o <<= 1) {
        int t = __shfl_up_sync(0xffffffffu, s, o);
        if (lane >= o) s += t;
    }
    if (lane == 31) wsum[wid] = s;
    __syncthreads();
    if (wid == 0) {
        int w = wsum[lane];
        #pragma unroll
        for (int o = 1; o < 32; o <<= 1) {
            int t = __shfl_up_sync(0xffffffffu, w, o);
            if (lane >= o) w += t;
        }
        wsum[lane] = w;
    }
    __syncthreads();
    int woff = (wid == 0) ? 0 : wsum[wid - 1];
    int ex = s - v + woff;
    if (i < n) {
        loc[i] = ex;
        dis[i] = rsqrtf((float)(v + 1));
    }
    if (tid == 0) g_tot[g * NCH_MAX + blockIdx.x] = wsum[31];
}

__global__ void scan_mid_kernel(int nch) {
    int g = threadIdx.x >> 5, lane = threadIdx.x & 31;
    int carry = 0;
    for (int c0 = 0; c0 < nch; c0 += 32) {
        int idx = c0 + lane;
        int v = (idx < nch) ? g_tot[g * NCH_MAX + idx] : 0;
        int s = v;
        #pragma unroll
        for (int o = 1; o < 32; o <<= 1) {
            int t = __shfl_up_sync(0xffffffffu, s, o);
            if (lane >= o) s += t;
        }
        if (idx < nch) g_off[g * NCH_MAX + idx] = carry + s - v;
        carry += __shfl_sync(0xffffffffu, s, 31);
    }
}

__global__ void scatter_kernel(const int* __restrict__ src_n,
                               const int* __restrict__ dst_n,
                               const int* __restrict__ src_r,
                               const int* __restrict__ dst_r, int E) {
    const int g = blockIdx.y;
    const int* __restrict__ src = g ? src_r : src_n;
    const int* __restrict__ dst = g ? dst_r : dst_n;
    const int* __restrict__ loc = g ? g_loc_role : g_loc_norm;
    int* __restrict__ fill      = g ? g_fill_role : g_fill_norm;
    int* __restrict__ col       = g ? g_col_role : g_col_norm;
    const int* off = &g_off[g * NCH_MAX];

    int e = blockIdx.x * blockDim.x + threadIdx.x;
    if (e < E) {
        int d = dst[e];
        int pos = loc[d] + off[d >> 10] + atomicAdd(&fill[d], 1);
        col[pos] = src[e];
    }
}

// ---------------------------------------------------------------------------
// Tensor-core GEMM: H = (X @ W) * dis[row], X fp32 split to bf16 hi/lo on load.
// BM=128, BN=128 (full), BK=32, 512 threads = 16 warps (4x4), warp tile 32x32.
// mma.sync.m16n8k16.f32.bf16.bf16.f32; acc += Ah*Bh + Ah*Bl + Al*Bh.
// ---------------------------------------------------------------------------
#define MMA16816(d, a, b)                                                     \
    asm volatile(                                                             \
        "mma.sync.aligned.m16n8k16.row.col.f32.bf16.bf16.f32 "                \
        "{%0,%1,%2,%3}, {%4,%5,%6,%7}, {%8,%9}, {%0,%1,%2,%3};"               \
        : "+f"((d)[0]), "+f"((d)[1]), "+f"((d)[2]), "+f"((d)[3])              \
        : "r"((a)[0]), "r"((a)[1]), "r"((a)[2]), "r"((a)[3]),                 \
          "r"((b)[0]), "r"((b)[1]))

#define SROW 40   // bf16 per smem row: 32 data + 8 pad (conflict-free)

__global__ __launch_bounds__(512) void gemm_tc_kernel(
    const float* __restrict__ X,
    const __nv_bfloat16* __restrict__ WTh,
    const __nv_bfloat16* __restrict__ WTl,
    const float* __restrict__ dis, float* __restrict__ H, int M)
{
    __shared__ __align__(16) __nv_bfloat16 As_h[128 * SROW];
    __shared__ __align__(16) __nv_bfloat16 As_l[128 * SROW];
    __shared__ __align__(16) __nv_bfloat16 Bs_h[128 * SROW];
    __shared__ __align__(16) __nv_bfloat16 Bs_l[128 * SROW];

    const int t    = threadIdx.x;
    const int lane = t & 31, wid = t >> 5;
    const int wm = wid >> 2;          // 0..3 : rows wm*32
    const int wn = wid & 3;           // 0..3 : cols wn*32
    const int gp = lane >> 2;         // group id 0..7
    const int tg = lane & 3;          // thread in group
    const int row0 = blockIdx.x * 128;

    const unsigned int* Ah32  = (const unsigned int*)As_h;
    const unsigned int* Al32  = (const unsigned int*)As_l;
    const unsigned int* Bh32r = (const unsigned int*)Bs_h;
    const unsigned int* Bl32r = (const unsigned int*)Bs_l;
    unsigned int* Bh32w = (unsigned int*)Bs_h;
    unsigned int* Bl32w = (unsigned int*)Bs_l;
    const unsigned int* WTh32 = (const unsigned int*)WTh;
    const unsigned int* WTl32 = (const unsigned int*)WTl;
    const float4* X4 = (const float4*)X;

    float acc[2][4][4];
    #pragma unroll
    for (int mi = 0; mi < 2; mi++)
        #pragma unroll
        for (int ni = 0; ni < 4; ni++)
            #pragma unroll
            for (int j = 0; j < 4; j++) acc[mi][ni][j] = 0.f;

    for (int k0 = 0; k0 < 128; k0 += 32) {
        // ---- A tile: 128 x 32 fp32 -> split hi/lo into smem ----
        #pragma unroll
        for (int i = 0; i < 2; i++) {
            int f4 = i * 512 + t;                 // 0..1023
            int r = f4 >> 3, c4 = f4 & 7;
            float4 v = make_float4(0.f, 0.f, 0.f, 0.f);
            if (row0 + r < M) v = X4[(row0 + r) * 32 + (k0 >> 2) + c4];
            int base = r * SROW + c4 * 4;
            float vv[4] = {v.x, v.y, v.z, v.w};
            #pragma unroll
            for (int j = 0; j < 4; j++) {
                __nv_bfloat16 h = __float2bfloat16(vv[j]);
                __nv_bfloat16 l = __float2bfloat16(vv[j] - __bfloat162float(h));
                As_h[base + j] = h;
                As_l[base + j] = l;
            }
        }
        // ---- B tile: WT[n][k0..k0+31] hi/lo, 128 x 16 u32 each ----
        #pragma unroll
        for (int i = 0; i < 4; i++) {
            int f = i * 512 + t;                  // 0..2047
            int nrow = f >> 4, kk2 = f & 15;
            Bh32w[nrow * (SROW / 2) + kk2] = WTh32[nrow * 64 + (k0 >> 1) + kk2];
            Bl32w[nrow * (SROW / 2) + kk2] = WTl32[nrow * 64 + (k0 >> 1) + kk2];
        }
        __syncthreads();

        #pragma unroll
        for (int kk = 0; kk < 32; kk += 16) {
            const int kc = (kk >> 1) + tg;        // u32 index within row
            unsigned int aH[2][4], aL[2][4], bH[4][2], bL[4][2];
            #pragma unroll
            for (int mi = 0; mi < 2; mi++) {
                int r = wm * 32 + mi * 16 + gp;
                aH[mi][0] = Ah32[r * (SROW / 2) + kc];
                aH[mi][1] = Ah32[(r + 8) * (SROW / 2) + kc];
                aH[mi][2] = Ah32[r * (SROW / 2) + kc + 4];
                aH[mi][3] = Ah32[(r + 8) * (SROW / 2) + kc + 4];
                aL[mi][0] = Al32[r * (SROW / 2) + kc];
                aL[mi][1] = Al32[(r + 8) * (SROW / 2) + kc];
                aL[mi][2] = Al32[r * (SROW / 2) + kc + 4];
                aL[mi][3] = Al32[(r + 8) * (SROW / 2) + kc + 4];
            }
            #pragma unroll
            for (int ni = 0; ni < 4; ni++) {
                int nn = wn * 32 + ni * 8 + gp;
                bH[ni][0] = Bh32r[nn * (SROW / 2) + kc];
                bH[ni][1] = Bh32r[nn * (SROW / 2) + kc + 4];
                bL[ni][0] = Bl32r[nn * (SROW / 2) + kc];
                bL[ni][1] = Bl32r[nn * (SROW / 2) + kc + 4];
            }
            #pragma unroll
            for (int mi = 0; mi < 2; mi++)
                #pragma unroll
                for (int ni = 0; ni < 4; ni++) {
                    MMA16816(acc[mi][ni], aH[mi], bH[ni]);
                    MMA16816(acc[mi][ni], aH[mi], bL[ni]);
                    MMA16816(acc[mi][ni], aL[mi], bH[ni]);
                }
        }
        __syncthreads();
    }

    // ---- epilogue: scale by dis[row], store fp32 ----
    #pragma unroll
    for (int mi = 0; mi < 2; mi++) {
        int r0 = row0 + wm * 32 + mi * 16 + gp;
        int r1 = r0 + 8;
        float s0 = (r0 < M) ? dis[r0] : 0.f;
        float s1 = (r1 < M) ? dis[r1] : 0.f;
        #pragma unroll
        for (int ni = 0; ni < 4; ni++) {
            int c = wn * 32 + ni * 8 + tg * 2;
            if (r0 < M) {
                float2 o = make_float2(acc[mi][ni][0] * s0, acc[mi][ni][1] * s0);
                *(float2*)&H[r0 * 128 + c] = o;
            }
            if (r1 < M) {
                float2 o = make_float2(acc[mi][ni][2] * s1, acc[mi][ni][3] * s1);
                *(float2*)&H[r1 * 128 + c] = o;
            }
        }
    }
}

// ---------------------------------------------------------------------------
// Aggregation: warp per node, lane holds channels [lane*4, lane*4+4)
// ---------------------------------------------------------------------------
template <bool RELU>
__global__ __launch_bounds__(256) void aggregate_kernel(
    const float* __restrict__ h, const int* __restrict__ loc,
    const int* __restrict__ off, const int* __restrict__ col,
    const float* __restrict__ dis, const float* __restrict__ bias,
    float* __restrict__ out, int n, int E)
{
    int w    = (blockIdx.x * blockDim.x + threadIdx.x) >> 5;
    int lane = threadIdx.x & 31;
    if (w >= n) return;

    int beg = loc[w] + off[w >> 10];
    int end = (w + 1 < n) ? (loc[w + 1] + off[(w + 1) >> 10]) : E;

    const float4* h4 = (const float4*)h;
    float4 acc = __ldg(&h4[w * 32 + lane]);   // self loop

    int j = beg;
    for (; j + 4 <= end; j += 4) {
        int s0 = __ldg(&col[j]);
        int s1 = __ldg(&col[j + 1]);
        int s2 = __ldg(&col[j + 2]);
        int s3 = __ldg(&col[j + 3]);
        float4 a0 = __ldg(&h4[s0 * 32 + lane]);
        float4 a1 = __ldg(&h4[s1 * 32 + lane]);
        float4 a2 = __ldg(&h4[s2 * 32 + lane]);
        float4 a3 = __ldg(&h4[s3 * 32 + lane]);
        acc.x += (a0.x + a1.x) + (a2.x + a3.x);
        acc.y += (a0.y + a1.y) + (a2.y + a3.y);
        acc.z += (a0.z + a1.z) + (a2.z + a3.z);
        acc.w += (a0.w + a1.w) + (a2.w + a3.w);
    }
    for (; j < end; j++) {
        int s = __ldg(&col[j]);
        float4 a = __ldg(&h4[s * 32 + lane]);
        acc.x += a.x; acc.y += a.y; acc.z += a.z; acc.w += a.w;
    }

    float dv = dis[w];
    float4 bv = ((const float4*)bias)[lane];
    acc.x = acc.x * dv + bv.x;
    acc.y = acc.y * dv + bv.y;
    acc.z = acc.z * dv + bv.z;
    acc.w = acc.w * dv + bv.w;
    if (RELU) {
        acc.x = fmaxf(acc.x, 0.f); acc.y = fmaxf(acc.y, 0.f);
        acc.z = fmaxf(acc.z, 0.f); acc.w = fmaxf(acc.w, 0.f);
    }
    ((float4*)out)[w * 32 + lane] = acc;
}

// ---------------------------------------------------------------------------
extern "C" void kernel_launch(void* const* d_in, const int* in_sizes, int n_in,
                              void* d_out, int out_size)
{
    const float* x      = (const float*)d_in[0];
    const float* W_role = (const float*)d_in[1];
    const float* b_role = (const float*)d_in[2];
    const float* W2     = (const float*)d_in[3];
    const float* b2     = (const float*)d_in[4];
    const float* W1     = (const float*)d_in[5];
    const float* b1     = (const float*)d_in[6];
    const int*   ei_nrm = (const int*)d_in[7];
    const int*   ei_rol = (const int*)d_in[8];

    const int n = in_sizes[0] / D;       // 50000
    const int E = in_sizes[7] / 2;       // 640000

    const int* src_n = ei_nrm;
    const int* dst_n = ei_nrm + E;
    const int* src_r = ei_rol;
    const int* dst_r = ei_rol + E;

    float *h_s, *act, *dis_r, *dis_n;
    int *loc_r, *loc_n, *col_r, *col_n, *off_d;
    __nv_bfloat16 *wth, *wtl;
    cudaGetSymbolAddress((void**)&h_s,   g_h);
    cudaGetSymbolAddress((void**)&act,   g_a);
    cudaGetSymbolAddress((void**)&dis_r, g_dis_role);
    cudaGetSymbolAddress((void**)&dis_n, g_dis_norm);
    cudaGetSymbolAddress((void**)&loc_r, g_loc_role);
    cudaGetSymbolAddress((void**)&loc_n, g_loc_norm);
    cudaGetSymbolAddress((void**)&col_r, g_col_role);
    cudaGetSymbolAddress((void**)&col_n, g_col_norm);
    cudaGetSymbolAddress((void**)&off_d, g_off);
    cudaGetSymbolAddress((void**)&wth,   g_WTh);
    cudaGetSymbolAddress((void**)&wtl,   g_WTl);

    const int TB  = 256;
    const int nbN = (n + TB - 1) / TB;
    const int nbE = (E + TB - 1) / TB;
    const int nch = (n + 1023) >> 10;

    const int gemmBlocks = (n + 127) / 128;
    const int aggBlocks  = (n + 7) / 8;

    // launch idx:                                                         deps
    prep_kernel<<<nbN, TB>>>(W_role, W2, W1, n);                       // 0
    count_kernel<<<nbE, TB>>>(dst_n, dst_r, E);                        // 1
    scan_local_kernel<<<dim3(nch, 2), 1024>>>(n);                      // 2 (dis)
    // gemm1 only needs dis_r + split weights -> launch idx 3 (ncu target)
    gemm_tc_kernel<<<gemmBlocks, 512>>>(x, wth, wtl, dis_r, h_s, n);   // 3
    scan_mid_kernel<<<1, 64>>>(nch);                                   // 4
    scatter_kernel<<<dim3(nbE, 2), TB>>>(src_n, dst_n, src_r, dst_r, E); // 5

    // ---- layer 1 aggregate (role graph), relu ----
    aggregate_kernel<true><<<aggBlocks, 256>>>(h_s, loc_r, off_d + NCH_MAX,
                                               col_r, dis_r, b_role, act, n, E);
    // ---- layer 2: normal graph, relu ----
    gemm_tc_kernel<<<gemmBlocks, 512>>>(act, wth + D * D, wtl + D * D,
                                        dis_n, h_s, n);
    aggregate_kernel<true><<<aggBlocks, 256>>>(h_s, loc_n, off_d,
                                               col_n, dis_n, b2, act, n, E);
    // ---- layer 3: normal graph, no relu, write d_out ----
    gemm_tc_kernel<<<gemmBlocks, 512>>>(act, wth + 2 * D * D, wtl + 2 * D * D,
                                        dis_n, h_s, n);
    aggregate_kernel<false><<<aggBlocks, 256>>>(h_s, loc_n, off_d,
                                                col_n, dis_n, b1,
                                                (float*)d_out, n, E);
}

// round 9
// speedup vs baseline: 2.0454x; 1.1099x over previous
#include <cuda_runtime.h>
#include <cuda_bf16.h>
#include <cstdint>
#include <stdint.h>

// ---------------------------------------------------------------------------
// 3-layer GCN:  relu(gcn(x,Wr)) -> relu(gcn(.,W2)) -> gcn(.,W1)
// gcn(x,W): out[v] = dis[v]*( sum_{s->v} h_s[s] + h_s[v] ) + b
//           where h_s = (x@W) * dis[row],  dis = rsqrt(indeg+1)
// GEMM: tensor cores, bf16 hi/lo split (3x mma), ldmatrix + cp.async pipeline.
// ---------------------------------------------------------------------------

#define N_MAX 50000
#define E_MAX 640000
#define D     128
#define NCH_MAX 64

// scratch (static device memory: allocation-free rule)
__device__ float g_h[N_MAX * D];        // h_scaled
__device__ float g_a[N_MAX * D];        // layer activation
__device__ float g_dis_role[N_MAX];
__device__ float g_dis_norm[N_MAX];
__device__ int   g_cnt_role[N_MAX];
__device__ int   g_cnt_norm[N_MAX];
__device__ int   g_fill_role[N_MAX];
__device__ int   g_fill_norm[N_MAX];
__device__ int   g_loc_role[N_MAX];
__device__ int   g_loc_norm[N_MAX];
__device__ int   g_tot[2 * NCH_MAX];
__device__ int   g_off[2 * NCH_MAX];
__device__ int   g_col_role[E_MAX];
__device__ int   g_col_norm[E_MAX];
// split+transposed weights: [w][n][k] bf16 hi / lo
__device__ __align__(16) __nv_bfloat16 g_WTh[3 * D * D];
__device__ __align__(16) __nv_bfloat16 g_WTl[3 * D * D];

// ---------------------------------------------------------------------------
__global__ void prep_kernel(const float* __restrict__ Wr,
                            const float* __restrict__ W2,
                            const float* __restrict__ W1, int n) {
    int i = blockIdx.x * blockDim.x + threadIdx.x;
    if (i < n) {
        g_cnt_role[i]  = 0;
        g_cnt_norm[i]  = 0;
        g_fill_role[i] = 0;
        g_fill_norm[i] = 0;
    }
    if (i < 3 * D * D) {
        int w = i >> 14, rem = i & 16383;
        int k = rem >> 7, nn = rem & 127;
        const float* W = (w == 0) ? Wr : (w == 1) ? W2 : W1;
        float v = W[k * D + nn];
        __nv_bfloat16 h = __float2bfloat16(v);
        __nv_bfloat16 l = __float2bfloat16(v - __bfloat162float(h));
        g_WTh[w * D * D + nn * D + k] = h;   // [n][k] layout (col-major B)
        g_WTl[w * D * D + nn * D + k] = l;
    }
}

__global__ void count_kernel(const int* __restrict__ dst_n,
                             const int* __restrict__ dst_r, int E) {
    int e = blockIdx.x * blockDim.x + threadIdx.x;
    if (e < E) {
        atomicAdd(&g_cnt_norm[dst_n[e]], 1);
        atomicAdd(&g_cnt_role[dst_r[e]], 1);
    }
}

__global__ __launch_bounds__(1024) void scan_local_kernel(int n) {
    const int g = blockIdx.y;
    const int* __restrict__ cnt = g ? g_cnt_role : g_cnt_norm;
    int* __restrict__ loc       = g ? g_loc_role : g_loc_norm;
    float* __restrict__ dis     = g ? g_dis_role : g_dis_norm;

    __shared__ int wsum[32];
    int tid  = threadIdx.x;
    int lane = tid & 31, wid = tid >> 5;
    int i = (blockIdx.x << 10) + tid;
    int v = (i < n) ? cnt[i] : 0;

    int s = v;
    #pragma unroll
    for (int o = 1; o < 32; o <<= 1) {
        int t = __shfl_up_sync(0xffffffffu, s, o);
        if (lane >= o) s += t;
    }
    if (lane == 31) wsum[wid] = s;
    __syncthreads();
    if (wid == 0) {
        int w = wsum[lane];
        #pragma unroll
        for (int o = 1; o < 32; o <<= 1) {
            int t = __shfl_up_sync(0xffffffffu, w, o);
            if (lane >= o) w += t;
        }
        wsum[lane] = w;
    }
    __syncthreads();
    int woff = (wid == 0) ? 0 : wsum[wid - 1];
    int ex = s - v + woff;
    if (i < n) {
        loc[i] = ex;
        dis[i] = rsqrtf((float)(v + 1));
    }
    if (tid == 0) g_tot[g * NCH_MAX + blockIdx.x] = wsum[31];
}

__global__ void scan_mid_kernel(int nch) {
    int g = threadIdx.x >> 5, lane = threadIdx.x & 31;
    int carry = 0;
    for (int c0 = 0; c0 < nch; c0 += 32) {
        int idx = c0 + lane;
        int v = (idx < nch) ? g_tot[g * NCH_MAX + idx] : 0;
        int s = v;
        #pragma unroll
        for (int o = 1; o < 32; o <<= 1) {
            int t = __shfl_up_sync(0xffffffffu, s, o);
            if (lane >= o) s += t;
        }
        if (idx < nch) g_off[g * NCH_MAX + idx] = carry + s - v;
        carry += __shfl_sync(0xffffffffu, s, 31);
    }
}

__global__ void scatter_kernel(const int* __restrict__ src_n,
                               const int* __restrict__ dst_n,
                               const int* __restrict__ src_r,
                               const int* __restrict__ dst_r, int E) {
    const int g = blockIdx.y;
    const int* __restrict__ src = g ? src_r : src_n;
    const int* __restrict__ dst = g ? dst_r : dst_n;
    const int* __restrict__ loc = g ? g_loc_role : g_loc_norm;
    int* __restrict__ fill      = g ? g_fill_role : g_fill_norm;
    int* __restrict__ col       = g ? g_col_role : g_col_norm;
    const int* off = &g_off[g * NCH_MAX];

    int e = blockIdx.x * blockDim.x + threadIdx.x;
    if (e < E) {
        int d = dst[e];
        int pos = loc[d] + off[d >> 10] + atomicAdd(&fill[d], 1);
        col[pos] = src[e];
    }
}

// ---------------------------------------------------------------------------
// Tensor-core GEMM: H = (X @ W) * dis[row].
// BM=64, BN=128, BK=32, 256 threads = 8 warps (2x4), warp tile 32x32.
// A: fp32 -> bf16 hi/lo split on load (reg-staged, double-buffered smem).
// B: pre-split bf16 in gmem, cp.async double-buffered.
// Fragments via ldmatrix.x4; acc += Ah*Bh + Ah*Bl + Al*Bh.
// ---------------------------------------------------------------------------
#define SROW 40          // bf16 per smem row (80 B): 16B-aligned, LDSM conflict-free
#define A_STAGE_BYTES 10240u   // 64*40*2 (hi) ... hi+lo = 2*5120
#define B_STAGE_BYTES 20480u   // 128*40*2 * 2 (hi+lo)
#define SMEM_TOTAL_GEMM (2u * A_STAGE_BYTES + 2u * B_STAGE_BYTES)  // 61440

#define MMA16816(d, a, b0, b1)                                                \
    asm volatile(                                                             \
        "mma.sync.aligned.m16n8k16.row.col.f32.bf16.bf16.f32 "                \
        "{%0,%1,%2,%3}, {%4,%5,%6,%7}, {%8,%9}, {%0,%1,%2,%3};"               \
        : "+f"((d)[0]), "+f"((d)[1]), "+f"((d)[2]), "+f"((d)[3])              \
        : "r"((a)[0]), "r"((a)[1]), "r"((a)[2]), "r"((a)[3]),                 \
          "r"(b0), "r"(b1))

#define LDSM4(r, addr)                                                        \
    asm volatile(                                                             \
        "ldmatrix.sync.aligned.m8n8.x4.shared.b16 {%0,%1,%2,%3}, [%4];"       \
        : "=r"((r)[0]), "=r"((r)[1]), "=r"((r)[2]), "=r"((r)[3])              \
        : "r"(addr))

__device__ __forceinline__ void cp16(uint32_t dst, const void* src) {
    asm volatile("cp.async.cg.shared.global [%0], [%1], 16;"
                 :: "r"(dst), "l"(src));
}

__global__ __launch_bounds__(256, 3) void gemm_tc_kernel(
    const float* __restrict__ X,
    const __nv_bfloat16* __restrict__ WTh,
    const __nv_bfloat16* __restrict__ WTl,
    const float* __restrict__ dis, float* __restrict__ H, int M)
{
    extern __shared__ char sm[];
    const uint32_t sbase = (uint32_t)__cvta_generic_to_shared(sm);
    // layout: A stage0 (hi|lo 5120 each), A stage1, B stage0 (hi|lo 10240), B stage1
    const uint32_t aH0 = sbase;
    const uint32_t bH0 = sbase + 2u * A_STAGE_BYTES;

    const int t    = threadIdx.x;
    const int lane = t & 31, wid = t >> 5;
    const int wm = wid >> 2;          // 0..1 : rows wm*32
    const int wn = wid & 3;           // 0..3 : cols wn*32
    const int gp = lane >> 2;
    const int tg = lane & 3;
    const int row0 = blockIdx.x * 64;

    // ldmatrix lane address components
    const int laneRowA = (lane & 7) + ((lane >> 3) & 1) * 8;
    const int laneKA   = (lane >> 4) * 16;                 // bytes
    const int laneRowB = (lane & 7) + ((lane >> 4) & 1) * 8;
    const int laneKB   = ((lane >> 3) & 1) * 16;           // bytes

    const float4* X4 = (const float4*)X;
    const uint4*  B4h = (const uint4*)WTh;
    const uint4*  B4l = (const uint4*)WTl;

    float acc[2][4][4];
    #pragma unroll
    for (int mi = 0; mi < 2; mi++)
        #pragma unroll
        for (int ni = 0; ni < 4; ni++)
            #pragma unroll
            for (int j = 0; j < 4; j++) acc[mi][ni][j] = 0.f;

    // per-thread load coords
    const int ar0 = t >> 3,  ac4 = t & 7;       // A: rows ar0, ar0+32
    const int br0 = t >> 2,  bc  = t & 3;       // B: rows br0, br0+64

    float4 aReg[2];

    // helper lambdas (inlined)
    auto loadA = [&](int k0) {
        #pragma unroll
        for (int i = 0; i < 2; i++) {
            int r = ar0 + i * 32;
            aReg[i] = (row0 + r < M)
                ? X4[(size_t)(row0 + r) * 32 + (k0 >> 2) + ac4]
                : make_float4(0.f, 0.f, 0.f, 0.f);
        }
    };
    auto stsA = [&](int s) {
        #pragma unroll
        for (int i = 0; i < 2; i++) {
            int r = ar0 + i * 32;
            float4 v = aReg[i];
            __nv_bfloat16 hx = __float2bfloat16(v.x);
            __nv_bfloat16 hy = __float2bfloat16(v.y);
            __nv_bfloat16 hz = __float2bfloat16(v.z);
            __nv_bfloat16 hw = __float2bfloat16(v.w);
            __nv_bfloat16 lx = __float2bfloat16(v.x - __bfloat162float(hx));
            __nv_bfloat16 ly = __float2bfloat16(v.y - __bfloat162float(hy));
            __nv_bfloat16 lz = __float2bfloat16(v.z - __bfloat162float(hz));
            __nv_bfloat16 lw = __float2bfloat16(v.w - __bfloat162float(hw));
            uint2 hv, lv;
            hv.x = (uint32_t)__bfloat16_as_ushort(hx) |
                   ((uint32_t)__bfloat16_as_ushort(hy) << 16);
            hv.y = (uint32_t)__bfloat16_as_ushort(hz) |
                   ((uint32_t)__bfloat16_as_ushort(hw) << 16);
            lv.x = (uint32_t)__bfloat16_as_ushort(lx) |
                   ((uint32_t)__bfloat16_as_ushort(ly) << 16);
            lv.y = (uint32_t)__bfloat16_as_ushort(lz) |
                   ((uint32_t)__bfloat16_as_ushort(lw) << 16);
            char* base = sm + s * A_STAGE_BYTES;
            *(uint2*)(base + r * 80 + ac4 * 8)        = hv;   // hi half
            *(uint2*)(base + 5120 + r * 80 + ac4 * 8) = lv;   // lo half
        }
    };
    auto cpB = [&](int s, int k0) {
        uint32_t dst = bH0 + (uint32_t)s * B_STAGE_BYTES;
        #pragma unroll
        for (int i = 0; i < 2; i++) {
            int r = br0 + i * 64;
            uint32_t doff = (uint32_t)(r * 80 + bc * 16);
            cp16(dst + doff,          B4h + r * 16 + (k0 >> 3) + bc);
            cp16(dst + 10240u + doff, B4l + r * 16 + (k0 >> 3) + bc);
        }
        asm volatile("cp.async.commit_group;");
    };

    // ---- prologue: stage 0 = k0 0 ----
    loadA(0);
    cpB(0, 0);
    stsA(0);
    asm volatile("cp.async.wait_group 0;");
    __syncthreads();

    int s = 0;
    #pragma unroll
    for (int k0i = 0; k0i < 4; k0i++) {
        const bool hasNext = (k0i < 3);
        if (hasNext) {
            loadA((k0i + 1) * 32);
            cpB(s ^ 1, (k0i + 1) * 32);
        }
        // ---- compute on stage s ----
        const uint32_t aH = sbase + (uint32_t)s * A_STAGE_BYTES;
        const uint32_t aL = aH + 5120u;
        const uint32_t bH = bH0 + (uint32_t)s * B_STAGE_BYTES;
        const uint32_t bL = bH + 10240u;
        #pragma unroll
        for (int kk = 0; kk < 32; kk += 16) {
            uint32_t bh[2][4], bl[2][4];
            #pragma unroll
            for (int pair = 0; pair < 2; pair++) {
                uint32_t off = (uint32_t)((wn * 32 + pair * 16 + laneRowB) * 80
                                          + kk * 2 + laneKB);
                LDSM4(bh[pair], bH + off);
                LDSM4(bl[pair], bL + off);
            }
            #pragma unroll
            for (int mi = 0; mi < 2; mi++) {
                uint32_t ah[4], al[4];
                uint32_t off = (uint32_t)((wm * 32 + mi * 16 + laneRowA) * 80
                                          + kk * 2 + laneKA);
                LDSM4(ah, aH + off);
                LDSM4(al, aL + off);
                #pragma unroll
                for (int ni = 0; ni < 4; ni++) {
                    int pair = ni >> 1, sb = (ni & 1) * 2;
                    MMA16816(acc[mi][ni], ah, bh[pair][sb], bh[pair][sb + 1]);
                    MMA16816(acc[mi][ni], ah, bl[pair][sb], bl[pair][sb + 1]);
                    MMA16816(acc[mi][ni], al, bh[pair][sb], bh[pair][sb + 1]);
                }
            }
        }
        if (hasNext) stsA(s ^ 1);
        asm volatile("cp.async.wait_group 0;");
        __syncthreads();
        s ^= 1;
    }

    // ---- epilogue: scale by dis[row], store fp32 ----
    #pragma unroll
    for (int mi = 0; mi < 2; mi++) {
        int r0g = row0 + wm * 32 + mi * 16 + gp;
        int r1g = r0g + 8;
        float s0 = (r0g < M) ? dis[r0g] : 0.f;
        float s1 = (r1g < M) ? dis[r1g] : 0.f;
        #pragma unroll
        for (int ni = 0; ni < 4; ni++) {
            int c = wn * 32 + (ni >> 1) * 16 + (ni & 1) * 8 + tg * 2;
            if (r0g < M) {
                float2 o = make_float2(acc[mi][ni][0] * s0, acc[mi][ni][1] * s0);
                *(float2*)&H[(size_t)r0g * 128 + c] = o;
            }
            if (r1g < M) {
                float2 o = make_float2(acc[mi][ni][2] * s1, acc[mi][ni][3] * s1);
                *(float2*)&H[(size_t)r1g * 128 + c] = o;
            }
        }
    }
}

// ---------------------------------------------------------------------------
// Aggregation: warp per node, lane holds channels [lane*4, lane*4+4)
// ---------------------------------------------------------------------------
template <bool RELU>
__global__ __launch_bounds__(256) void aggregate_kernel(
    const float* __restrict__ h, const int* __restrict__ loc,
    const int* __restrict__ off, const int* __restrict__ col,
    const float* __restrict__ dis, const float* __restrict__ bias,
    float* __restrict__ out, int n, int E)
{
    int w    = (blockIdx.x * blockDim.x + threadIdx.x) >> 5;
    int lane = threadIdx.x & 31;
    if (w >= n) return;

    int beg = loc[w] + off[w >> 10];
    int end = (w + 1 < n) ? (loc[w + 1] + off[(w + 1) >> 10]) : E;

    const float4* h4 = (const float4*)h;
    float4 acc = __ldg(&h4[w * 32 + lane]);   // self loop

    int j = beg;
    for (; j + 4 <= end; j += 4) {
        int s0 = __ldg(&col[j]);
        int s1 = __ldg(&col[j + 1]);
        int s2 = __ldg(&col[j + 2]);
        int s3 = __ldg(&col[j + 3]);
        float4 a0 = __ldg(&h4[s0 * 32 + lane]);
        float4 a1 = __ldg(&h4[s1 * 32 + lane]);
        float4 a2 = __ldg(&h4[s2 * 32 + lane]);
        float4 a3 = __ldg(&h4[s3 * 32 + lane]);
        acc.x += (a0.x + a1.x) + (a2.x + a3.x);
        acc.y += (a0.y + a1.y) + (a2.y + a3.y);
        acc.z += (a0.z + a1.z) + (a2.z + a3.z);
        acc.w += (a0.w + a1.w) + (a2.w + a3.w);
    }
    for (; j < end; j++) {
        int s = __ldg(&col[j]);
        float4 a = __ldg(&h4[s * 32 + lane]);
        acc.x += a.x; acc.y += a.y; acc.z += a.z; acc.w += a.w;
    }

    float dv = dis[w];
    float4 bv = ((const float4*)bias)[lane];
    acc.x = acc.x * dv + bv.x;
    acc.y = acc.y * dv + bv.y;
    acc.z = acc.z * dv + bv.z;
    acc.w = acc.w * dv + bv.w;
    if (RELU) {
        acc.x = fmaxf(acc.x, 0.f); acc.y = fmaxf(acc.y, 0.f);
        acc.z = fmaxf(acc.z, 0.f); acc.w = fmaxf(acc.w, 0.f);
    }
    ((float4*)out)[w * 32 + lane] = acc;
}

// ---------------------------------------------------------------------------
extern "C" void kernel_launch(void* const* d_in, const int* in_sizes, int n_in,
                              void* d_out, int out_size)
{
    const float* x      = (const float*)d_in[0];
    const float* W_role = (const float*)d_in[1];
    const float* b_role = (const float*)d_in[2];
    const float* W2     = (const float*)d_in[3];
    const float* b2     = (const float*)d_in[4];
    const float* W1     = (const float*)d_in[5];
    const float* b1     = (const float*)d_in[6];
    const int*   ei_nrm = (const int*)d_in[7];
    const int*   ei_rol = (const int*)d_in[8];

    const int n = in_sizes[0] / D;       // 50000
    const int E = in_sizes[7] / 2;       // 640000

    const int* src_n = ei_nrm;
    const int* dst_n = ei_nrm + E;
    const int* src_r = ei_rol;
    const int* dst_r = ei_rol + E;

    float *h_s, *act, *dis_r, *dis_n;
    int *loc_r, *loc_n, *col_r, *col_n, *off_d;
    __nv_bfloat16 *wth, *wtl;
    cudaGetSymbolAddress((void**)&h_s,   g_h);
    cudaGetSymbolAddress((void**)&act,   g_a);
    cudaGetSymbolAddress((void**)&dis_r, g_dis_role);
    cudaGetSymbolAddress((void**)&dis_n, g_dis_norm);
    cudaGetSymbolAddress((void**)&loc_r, g_loc_role);
    cudaGetSymbolAddress((void**)&loc_n, g_loc_norm);
    cudaGetSymbolAddress((void**)&col_r, g_col_role);
    cudaGetSymbolAddress((void**)&col_n, g_col_norm);
    cudaGetSymbolAddress((void**)&off_d, g_off);
    cudaGetSymbolAddress((void**)&wth,   g_WTh);
    cudaGetSymbolAddress((void**)&wtl,   g_WTl);

    cudaFuncSetAttribute(gemm_tc_kernel,
                         cudaFuncAttributeMaxDynamicSharedMemorySize,
                         SMEM_TOTAL_GEMM);

    const int TB  = 256;
    const int nbN = (n + TB - 1) / TB;
    const int nbE = (E + TB - 1) / TB;
    const int nch = (n + 1023) >> 10;

    const int gemmBlocks = (n + 63) / 64;
    const int aggBlocks  = (n + 7) / 8;

    // launch idx:
    prep_kernel<<<nbN, TB>>>(W_role, W2, W1, n);                         // 0
    count_kernel<<<nbE, TB>>>(dst_n, dst_r, E);                          // 1
    scan_local_kernel<<<dim3(nch, 2), 1024>>>(n);                        // 2
    // gemm1 only needs dis_r + split weights -> launch idx 3 (ncu target)
    gemm_tc_kernel<<<gemmBlocks, 256, SMEM_TOTAL_GEMM>>>(x, wth, wtl,
                                                         dis_r, h_s, n); // 3
    scan_mid_kernel<<<1, 64>>>(nch);                                     // 4
    scatter_kernel<<<dim3(nbE, 2), TB>>>(src_n, dst_n, src_r, dst_r, E); // 5

    // ---- layer 1 aggregate (role graph), relu ----
    aggregate_kernel<true><<<aggBlocks, 256>>>(h_s, loc_r, off_d + NCH_MAX,
                                               col_r, dis_r, b_role, act, n, E);
    // ---- layer 2: normal graph, relu ----
    gemm_tc_kernel<<<gemmBlocks, 256, SMEM_TOTAL_GEMM>>>(act, wth + D * D,
                                                         wtl + D * D,
                                                         dis_n, h_s, n);
    aggregate_kernel<true><<<aggBlocks, 256>>>(h_s, loc_n, off_d,
                                               col_n, dis_n, b2, act, n, E);
    // ---- layer 3: normal graph, no relu, write d_out ----
    gemm_tc_kernel<<<gemmBlocks, 256, SMEM_TOTAL_GEMM>>>(act, wth + 2 * D * D,
                                                         wtl + 2 * D * D,
                                                         dis_n, h_s, n);
    aggregate_kernel<false><<<aggBlocks, 256>>>(h_s, loc_n, off_d,
                                                col_n, dis_n, b1,
                                                (float*)d_out, n, E);
}